// round 5
// baseline (speedup 1.0000x reference)
#include <cuda_runtime.h>
#include <cuda_bf16.h>
#include <cstdint>

#define B_   32
#define N_   4096
#define C_   128
#define O_   128
#define M_   256
#define SPLITK 4

// ---------------- scratch (device globals; no allocation allowed) ----------
__device__ __align__(16) float g_outspec[B_ * M_ * O_];   // [b][m][o]
__device__ __align__(16) float g_wt[M_ * C_ * O_];        // [m][c][o]
__device__ __align__(16) float g_part[SPLITK * B_ * M_ * C_];  // split-K partials

__device__ __align__(128) __nv_bfloat16 g_Uhi[N_ * M_];   // [n][m]  (A for K3)
__device__ __align__(128) __nv_bfloat16 g_Ulo[N_ * M_];
__device__ __align__(128) __nv_bfloat16 g_Uthi[M_ * N_];  // [m][n]  (A for K1)
__device__ __align__(128) __nv_bfloat16 g_Utlo[M_ * N_];
__device__ __align__(128) __nv_bfloat16 g_xthi[(size_t)B_ * C_ * N_]; // [b][c][n] (B for K1)
__device__ __align__(128) __nv_bfloat16 g_xtlo[(size_t)B_ * C_ * N_];
__device__ __align__(128) __nv_bfloat16 g_sthi[B_ * O_ * M_];         // [b][o][m] (B for K3)
__device__ __align__(128) __nv_bfloat16 g_stlo[B_ * O_ * M_];

// ---------------- helpers ---------------------------------------------------
__device__ __forceinline__ uint32_t smem_u32(const void* p) {
    uint32_t a;
    asm("{ .reg .u64 t; cvta.to.shared.u64 t, %1; cvt.u32.u64 %0, t; }" : "=r"(a) : "l"(p));
    return a;
}
__device__ __forceinline__ void cp16(uint32_t dst, const void* src) {
    asm volatile("cp.async.cg.shared.global [%0], [%1], 16;" :: "r"(dst), "l"(src));
}
__device__ __forceinline__ void cp_commit() {
    asm volatile("cp.async.commit_group;" ::: "memory");
}
__device__ __forceinline__ void ldsm4(uint32_t& r0, uint32_t& r1, uint32_t& r2, uint32_t& r3,
                                      uint32_t addr) {
    asm volatile("ldmatrix.sync.aligned.m8n8.x4.shared.b16 {%0,%1,%2,%3}, [%4];"
                 : "=r"(r0), "=r"(r1), "=r"(r2), "=r"(r3) : "r"(addr));
}
__device__ __forceinline__ void mma_bf16(float* d, const uint32_t* a, const uint32_t* b) {
    asm volatile("mma.sync.aligned.m16n8k16.row.col.f32.bf16.bf16.f32 "
                 "{%0,%1,%2,%3}, {%4,%5,%6,%7}, {%8,%9}, {%0,%1,%2,%3};"
                 : "+f"(d[0]), "+f"(d[1]), "+f"(d[2]), "+f"(d[3])
                 : "r"(a[0]), "r"(a[1]), "r"(a[2]), "r"(a[3]), "r"(b[0]), "r"(b[1]));
}
__device__ __forceinline__ void split2(float v, __nv_bfloat16& h, __nv_bfloat16& l) {
    h = __float2bfloat16_rn(v);
    l = __float2bfloat16_rn(v - __bfloat162float(h));
}

// ---------------- prep kernels ---------------------------------------------
__global__ __launch_bounds__(256) void p1_splitU(const float* __restrict__ U) {
    __shared__ float t[32][33];
    const int m0 = blockIdx.x * 32, n0 = blockIdx.y * 32;
    const int tx = threadIdx.x, ty = threadIdx.y;
#pragma unroll
    for (int i = 0; i < 32; i += 8) {
        float v = U[(size_t)(n0 + ty + i) * M_ + m0 + tx];
        t[ty + i][tx] = v;
        __nv_bfloat16 h, l; split2(v, h, l);
        g_Uhi[(size_t)(n0 + ty + i) * M_ + m0 + tx] = h;
        g_Ulo[(size_t)(n0 + ty + i) * M_ + m0 + tx] = l;
    }
    __syncthreads();
#pragma unroll
    for (int i = 0; i < 32; i += 8) {
        float v = t[tx][ty + i];
        __nv_bfloat16 h, l; split2(v, h, l);
        g_Uthi[(size_t)(m0 + ty + i) * N_ + n0 + tx] = h;
        g_Utlo[(size_t)(m0 + ty + i) * N_ + n0 + tx] = l;
    }
}

__global__ __launch_bounds__(256) void p2_splitx(const float* __restrict__ x) {
    __shared__ float t[32][33];
    const int c0 = blockIdx.x * 32, n0 = blockIdx.y * 32, b = blockIdx.z;
    const int tx = threadIdx.x, ty = threadIdx.y;
#pragma unroll
    for (int i = 0; i < 32; i += 8)
        t[ty + i][tx] = x[((size_t)b * N_ + n0 + ty + i) * C_ + c0 + tx];
    __syncthreads();
#pragma unroll
    for (int i = 0; i < 32; i += 8) {
        float v = t[tx][ty + i];
        __nv_bfloat16 h, l; split2(v, h, l);
        g_xthi[((size_t)b * C_ + c0 + ty + i) * N_ + n0 + tx] = h;
        g_xtlo[((size_t)b * C_ + c0 + ty + i) * N_ + n0 + tx] = l;
    }
}

__global__ __launch_bounds__(256) void p3_splitS() {
    __shared__ float t[32][33];
    const int o0 = blockIdx.x * 32, m0 = blockIdx.y * 32, b = blockIdx.z;
    const int tx = threadIdx.x, ty = threadIdx.y;
#pragma unroll
    for (int i = 0; i < 32; i += 8)
        t[ty + i][tx] = g_outspec[((size_t)b * M_ + m0 + ty + i) * O_ + o0 + tx];
    __syncthreads();
#pragma unroll
    for (int i = 0; i < 32; i += 8) {
        float v = t[tx][ty + i];
        __nv_bfloat16 h, l; split2(v, h, l);
        g_sthi[((size_t)b * O_ + o0 + ty + i) * M_ + m0 + tx] = h;
        g_stlo[((size_t)b * O_ + o0 + ty + i) * M_ + m0 + tx] = l;
    }
}

__global__ __launch_bounds__(256) void k2a_transpose(const float* __restrict__ W) {
    __shared__ float t[32][33];
    const int co0 = blockIdx.x * 32, m0 = blockIdx.y * 32;
    const int tx = threadIdx.x, ty = threadIdx.y;
#pragma unroll
    for (int i = 0; i < 32; i += 8)
        t[ty + i][tx] = W[(size_t)(co0 + ty + i) * M_ + m0 + tx];
    __syncthreads();
#pragma unroll
    for (int i = 0; i < 32; i += 8)
        g_wt[(size_t)(m0 + ty + i) * (C_ * O_) + co0 + tx] = t[tx][ty + i];
}

// K2: out_spec[b,m,o] = sum_c x_spec[b,m,c] * Wt[m][c][o]; x_spec = sum of partials
__global__ __launch_bounds__(256) void k2_mix() {
    __shared__ float xs[B_][C_];
    const int m = blockIdx.x;
    const int tid = threadIdx.x;
    for (int i = tid; i < B_ * C_; i += 256) {
        int b = i >> 7, c = i & 127;
        const size_t idx = ((size_t)b * M_ + m) * C_ + c;
        float v = 0.f;
#pragma unroll
        for (int ks = 0; ks < SPLITK; ks++)
            v += g_part[(size_t)ks * (B_ * M_ * C_) + idx];
        xs[b][c] = v;
    }
    __syncthreads();
    const int o = tid & 127;
    const int bh = tid >> 7;
    const float* w = g_wt + (size_t)m * C_ * O_;
    float acc[16];
#pragma unroll
    for (int i = 0; i < 16; i++) acc[i] = 0.f;
#pragma unroll 4
    for (int c = 0; c < C_; c++) {
        float wv = w[c * O_ + o];
#pragma unroll
        for (int bb = 0; bb < 16; bb++)
            acc[bb] += xs[bb * 2 + bh][c] * wv;
    }
#pragma unroll
    for (int bb = 0; bb < 16; bb++)
        g_outspec[((size_t)(bb * 2 + bh) * M_ + m) * O_ + o] = acc[bb];
}

// ---------------- HMMA bf16-split GEMM: 4 warps, 64x64 warp tiles ----------
// KC=32 (64B rows), 3-stage cp.async, 2 CTAs/SM. swizzle: ch ^= (row>>1)&3.
#define KC        32
#define MATB      8192          // 128 rows x 64 B
#define STAGEB    32768         // 4 mats
#define GEMM_SMEM 98304         // 3 stages

template <int MODE>   // 0: K1 (split-K=SPLITK), 1: K3
__global__ __launch_bounds__(128, 2) void gemm_hmma(float* __restrict__ outp) {
    extern __shared__ char smem[];
    const uint32_t sb = smem_u32(smem);
    const int tid = threadIdx.x, wid = tid >> 5, lane = tid & 31;
    const int rt = blockIdx.x, ks = blockIdx.y, b = blockIdx.z;

    constexpr int LD   = (MODE == 0) ? N_ : M_;
    constexpr int KLEN = (MODE == 0) ? (N_ / SPLITK) : M_;
    constexpr int NS   = KLEN / KC;

    const __nv_bfloat16 *pAh, *pAl, *pBh, *pBl;
    float* po;
    if (MODE == 0) {
        const size_t aoff = (size_t)rt * 128 * N_ + (size_t)ks * KLEN;
        const size_t boff = (size_t)b * 128 * N_ + (size_t)ks * KLEN;
        pAh = g_Uthi + aoff; pAl = g_Utlo + aoff;
        pBh = g_xthi + boff; pBl = g_xtlo + boff;
        po = g_part + (size_t)ks * (B_ * M_ * C_) + (size_t)(b * 2 + rt) * (128 * 128);
    } else {
        const size_t aoff = (size_t)rt * 128 * M_;
        const size_t boff = (size_t)b * 128 * M_;
        pAh = g_Uhi + aoff; pAl = g_Ulo + aoff;
        pBh = g_sthi + boff; pBl = g_stlo + boff;
        po = outp + ((size_t)b * N_ + (size_t)rt * 128) * O_;
    }
    const __nv_bfloat16* mats[4] = {pAh, pAl, pBh, pBl};

    // stage loader: 4 mats x 128 rows x 4 chunks(16B); 2048 chunks / 128 thr
    auto load_stage = [&](int s, int kbase) {
        const uint32_t sd = sb + (uint32_t)(s % 3) * STAGEB;
#pragma unroll
        for (int mat = 0; mat < 4; mat++) {
            const __nv_bfloat16* bp = mats[mat];
#pragma unroll
            for (int j = 0; j < 4; j++) {
                const int rem = j * 128 + tid;        // 0..511
                const int row = rem >> 2, ch = rem & 3;
                const uint32_t dst = sd + mat * MATB + row * 64
                                   + ((ch ^ ((row >> 1) & 3)) << 4);
                cp16(dst, bp + (size_t)row * LD + kbase + ch * 8);
            }
        }
        cp_commit();
    };

    // warp grid 2(m) x 2(n); warp tile 64 x 64
    const int wm = wid >> 1, wn = wid & 1;
    const int lane15 = lane & 15, hk = lane >> 4;
    const uint32_t rowA = wm * 64 + lane15;
    const uint32_t rowB = wn * 64 + lane15;
    const uint32_t offA = rowA * 64, xorA = (rowA >> 1) & 3;
    const uint32_t offB = rowB * 64, xorB = (rowB >> 1) & 3;

    float acc[4][8][4];
#pragma unroll
    for (int i = 0; i < 4; i++)
#pragma unroll
        for (int j = 0; j < 8; j++)
#pragma unroll
            for (int r = 0; r < 4; r++) acc[i][j][r] = 0.f;

    load_stage(0, 0);
    load_stage(1, KC);
    load_stage(2, 2 * KC);

    for (int s = 0; s < NS; s++) {
        if (s + 2 < NS)      asm volatile("cp.async.wait_group 2;" ::: "memory");
        else if (s + 1 < NS) asm volatile("cp.async.wait_group 1;" ::: "memory");
        else                 asm volatile("cp.async.wait_group 0;" ::: "memory");
        __syncthreads();

        const uint32_t sd  = sb + (uint32_t)(s % 3) * STAGEB;
        const uint32_t sAh = sd,            sAl = sd + MATB;
        const uint32_t sBh = sd + 2 * MATB, sBl = sd + 3 * MATB;

#pragma unroll
        for (int kk = 0; kk < 2; kk++) {   // 2 k16 steps per stage
            const uint32_t chA = (uint32_t)(((2 * kk + hk) ^ xorA) << 4);
            const uint32_t chB = (uint32_t)(((2 * kk + hk) ^ xorB) << 4);
            uint32_t ah[4][4], al[4][4], bh[8][2], bl[8][2];
#pragma unroll
            for (int mi = 0; mi < 4; mi++) {
                ldsm4(ah[mi][0], ah[mi][1], ah[mi][2], ah[mi][3],
                      sAh + offA + mi * 1024 + chA);
                ldsm4(al[mi][0], al[mi][1], al[mi][2], al[mi][3],
                      sAl + offA + mi * 1024 + chA);
            }
#pragma unroll
            for (int nb = 0; nb < 4; nb++) {
                uint32_t r0, r1, r2, r3;
                ldsm4(r0, r1, r2, r3, sBh + offB + nb * 1024 + chB);
                bh[nb * 2 + 0][0] = r0; bh[nb * 2 + 0][1] = r2;
                bh[nb * 2 + 1][0] = r1; bh[nb * 2 + 1][1] = r3;
                ldsm4(r0, r1, r2, r3, sBl + offB + nb * 1024 + chB);
                bl[nb * 2 + 0][0] = r0; bl[nb * 2 + 0][1] = r2;
                bl[nb * 2 + 1][0] = r1; bl[nb * 2 + 1][1] = r3;
            }
            // product-major: long dependency-free mma runs
#pragma unroll
            for (int mi = 0; mi < 4; mi++)
#pragma unroll
                for (int ni = 0; ni < 8; ni++)
                    mma_bf16(acc[mi][ni], ah[mi], bh[ni]);   // hi*hi
#pragma unroll
            for (int mi = 0; mi < 4; mi++)
#pragma unroll
                for (int ni = 0; ni < 8; ni++)
                    mma_bf16(acc[mi][ni], ah[mi], bl[ni]);   // hi*lo
#pragma unroll
            for (int mi = 0; mi < 4; mi++)
#pragma unroll
                for (int ni = 0; ni < 8; ni++)
                    mma_bf16(acc[mi][ni], al[mi], bh[ni]);   // lo*hi
        }
        __syncthreads();
        if (s + 3 < NS) load_stage(s + 3, (s + 3) * KC);
    }

    const int er = (lane >> 2), ec = (lane & 3) * 2;
#pragma unroll
    for (int mi = 0; mi < 4; mi++) {
        const int r0 = wm * 64 + mi * 16 + er;
#pragma unroll
        for (int ni = 0; ni < 8; ni++) {
            const int c = wn * 64 + ni * 8 + ec;
            *(float2*)(po + (size_t)r0 * 128 + c)       = make_float2(acc[mi][ni][0], acc[mi][ni][1]);
            *(float2*)(po + (size_t)(r0 + 8) * 128 + c) = make_float2(acc[mi][ni][2], acc[mi][ni][3]);
        }
    }
}

// ---------------- launch ---------------------------------------------------
extern "C" void kernel_launch(void* const* d_in, const int* in_sizes, int n_in,
                              void* d_out, int out_size) {
    const float* x = (const float*)d_in[0];   // [B, N, C]
    const float* U = (const float*)d_in[1];   // [N, M]
    const float* W = (const float*)d_in[2];   // [C, O, M]
    float* out = (float*)d_out;               // [B, N, O]

    cudaFuncSetAttribute(gemm_hmma<0>, cudaFuncAttributeMaxDynamicSharedMemorySize, GEMM_SMEM);
    cudaFuncSetAttribute(gemm_hmma<1>, cudaFuncAttributeMaxDynamicSharedMemorySize, GEMM_SMEM);

    // prep: splits + transposes
    p1_splitU<<<dim3(M_ / 32, N_ / 32), dim3(32, 8)>>>(U);
    p2_splitx<<<dim3(C_ / 32, N_ / 32, B_), dim3(32, 8)>>>(x);
    k2a_transpose<<<dim3(C_ * O_ / 32, M_ / 32), dim3(32, 8)>>>(W);

    // K1: x_spec = U^T x  (HMMA, split-K=SPLITK; reduction fused into k2_mix)
    gemm_hmma<0><<<dim3(M_ / 128, SPLITK, B_), 128, GEMM_SMEM>>>(nullptr);

    // K2: per-mode channel mixing (fp32)
    k2_mix<<<M_, 256>>>();

    // split S for K3
    p3_splitS<<<dim3(O_ / 32, M_ / 32, B_), dim3(32, 8)>>>();

    // K3: out = U S  (HMMA)
    gemm_hmma<1><<<dim3(N_ / 128, 1, B_), 128, GEMM_SMEM>>>(out);
}

// round 6
// speedup vs baseline: 1.0261x; 1.0261x over previous
#include <cuda_runtime.h>
#include <cuda_bf16.h>
#include <cstdint>

#define B_   32
#define N_   4096
#define C_   128
#define O_   128
#define M_   256
#define SPLITK 4

// ---------------- scratch (device globals; no allocation allowed) ----------
__device__ __align__(16) float g_outspec[B_ * M_ * O_];   // [b][m][o]
__device__ __align__(16) float g_wt[M_ * C_ * O_];        // [m][c][o]
__device__ __align__(16) float g_part[SPLITK * B_ * M_ * C_];  // split-K partials

__device__ __align__(128) __nv_bfloat16 g_Uhi[N_ * M_];   // [n][m]  (A for K3)
__device__ __align__(128) __nv_bfloat16 g_Ulo[N_ * M_];
__device__ __align__(128) __nv_bfloat16 g_Uthi[M_ * N_];  // [m][n]  (A for K1)
__device__ __align__(128) __nv_bfloat16 g_Utlo[M_ * N_];
__device__ __align__(128) __nv_bfloat16 g_xthi[(size_t)B_ * C_ * N_]; // [b][c][n] (B for K1)
__device__ __align__(128) __nv_bfloat16 g_xtlo[(size_t)B_ * C_ * N_];
__device__ __align__(128) __nv_bfloat16 g_sthi[B_ * O_ * M_];         // [b][o][m] (B for K3)
__device__ __align__(128) __nv_bfloat16 g_stlo[B_ * O_ * M_];

// ---------------- helpers ---------------------------------------------------
__device__ __forceinline__ uint32_t smem_u32(const void* p) {
    uint32_t a;
    asm("{ .reg .u64 t; cvta.to.shared.u64 t, %1; cvt.u32.u64 %0, t; }" : "=r"(a) : "l"(p));
    return a;
}
__device__ __forceinline__ void cp16(uint32_t dst, const void* src) {
    asm volatile("cp.async.cg.shared.global [%0], [%1], 16;" :: "r"(dst), "l"(src));
}
__device__ __forceinline__ void cp_commit() {
    asm volatile("cp.async.commit_group;" ::: "memory");
}
__device__ __forceinline__ void ldsm4(uint32_t& r0, uint32_t& r1, uint32_t& r2, uint32_t& r3,
                                      uint32_t addr) {
    asm volatile("ldmatrix.sync.aligned.m8n8.x4.shared.b16 {%0,%1,%2,%3}, [%4];"
                 : "=r"(r0), "=r"(r1), "=r"(r2), "=r"(r3) : "r"(addr));
}
__device__ __forceinline__ void mma_bf16(float* d, const uint32_t* a, const uint32_t* b) {
    asm volatile("mma.sync.aligned.m16n8k16.row.col.f32.bf16.bf16.f32 "
                 "{%0,%1,%2,%3}, {%4,%5,%6,%7}, {%8,%9}, {%0,%1,%2,%3};"
                 : "+f"(d[0]), "+f"(d[1]), "+f"(d[2]), "+f"(d[3])
                 : "r"(a[0]), "r"(a[1]), "r"(a[2]), "r"(a[3]), "r"(b[0]), "r"(b[1]));
}
__device__ __forceinline__ void split2(float v, __nv_bfloat16& h, __nv_bfloat16& l) {
    h = __float2bfloat16_rn(v);
    l = __float2bfloat16_rn(v - __bfloat162float(h));
}

// ---------------- prep kernels ---------------------------------------------
__global__ __launch_bounds__(256) void p1_splitU(const float* __restrict__ U) {
    __shared__ float t[32][33];
    const int m0 = blockIdx.x * 32, n0 = blockIdx.y * 32;
    const int tx = threadIdx.x, ty = threadIdx.y;
#pragma unroll
    for (int i = 0; i < 32; i += 8) {
        float v = U[(size_t)(n0 + ty + i) * M_ + m0 + tx];
        t[ty + i][tx] = v;
        __nv_bfloat16 h, l; split2(v, h, l);
        g_Uhi[(size_t)(n0 + ty + i) * M_ + m0 + tx] = h;
        g_Ulo[(size_t)(n0 + ty + i) * M_ + m0 + tx] = l;
    }
    __syncthreads();
#pragma unroll
    for (int i = 0; i < 32; i += 8) {
        float v = t[tx][ty + i];
        __nv_bfloat16 h, l; split2(v, h, l);
        g_Uthi[(size_t)(m0 + ty + i) * N_ + n0 + tx] = h;
        g_Utlo[(size_t)(m0 + ty + i) * N_ + n0 + tx] = l;
    }
}

__global__ __launch_bounds__(256) void p2_splitx(const float* __restrict__ x) {
    __shared__ float t[32][33];
    const int c0 = blockIdx.x * 32, n0 = blockIdx.y * 32, b = blockIdx.z;
    const int tx = threadIdx.x, ty = threadIdx.y;
#pragma unroll
    for (int i = 0; i < 32; i += 8)
        t[ty + i][tx] = x[((size_t)b * N_ + n0 + ty + i) * C_ + c0 + tx];
    __syncthreads();
#pragma unroll
    for (int i = 0; i < 32; i += 8) {
        float v = t[tx][ty + i];
        __nv_bfloat16 h, l; split2(v, h, l);
        g_xthi[((size_t)b * C_ + c0 + ty + i) * N_ + n0 + tx] = h;
        g_xtlo[((size_t)b * C_ + c0 + ty + i) * N_ + n0 + tx] = l;
    }
}

__global__ __launch_bounds__(256) void p3_splitS() {
    __shared__ float t[32][33];
    const int o0 = blockIdx.x * 32, m0 = blockIdx.y * 32, b = blockIdx.z;
    const int tx = threadIdx.x, ty = threadIdx.y;
#pragma unroll
    for (int i = 0; i < 32; i += 8)
        t[ty + i][tx] = g_outspec[((size_t)b * M_ + m0 + ty + i) * O_ + o0 + tx];
    __syncthreads();
#pragma unroll
    for (int i = 0; i < 32; i += 8) {
        float v = t[tx][ty + i];
        __nv_bfloat16 h, l; split2(v, h, l);
        g_sthi[((size_t)b * O_ + o0 + ty + i) * M_ + m0 + tx] = h;
        g_stlo[((size_t)b * O_ + o0 + ty + i) * M_ + m0 + tx] = l;
    }
}

__global__ __launch_bounds__(256) void k2a_transpose(const float* __restrict__ W) {
    __shared__ float t[32][33];
    const int co0 = blockIdx.x * 32, m0 = blockIdx.y * 32;
    const int tx = threadIdx.x, ty = threadIdx.y;
#pragma unroll
    for (int i = 0; i < 32; i += 8)
        t[ty + i][tx] = W[(size_t)(co0 + ty + i) * M_ + m0 + tx];
    __syncthreads();
#pragma unroll
    for (int i = 0; i < 32; i += 8)
        g_wt[(size_t)(m0 + ty + i) * (C_ * O_) + co0 + tx] = t[tx][ty + i];
}

// K2: out_spec[b,m,o] = sum_c x_spec[b,m,c] * Wt[m][c][o]; x_spec = sum of partials
__global__ __launch_bounds__(256) void k2_mix() {
    __shared__ float xs[B_][C_];
    const int m = blockIdx.x;
    const int tid = threadIdx.x;
    for (int i = tid; i < B_ * C_; i += 256) {
        int b = i >> 7, c = i & 127;
        const size_t idx = ((size_t)b * M_ + m) * C_ + c;
        float v = 0.f;
#pragma unroll
        for (int ks = 0; ks < SPLITK; ks++)
            v += g_part[(size_t)ks * (B_ * M_ * C_) + idx];
        xs[b][c] = v;
    }
    __syncthreads();
    const int o = tid & 127;
    const int bh = tid >> 7;
    const float* w = g_wt + (size_t)m * C_ * O_;
    float acc[16];
#pragma unroll
    for (int i = 0; i < 16; i++) acc[i] = 0.f;
#pragma unroll 4
    for (int c = 0; c < C_; c++) {
        float wv = w[c * O_ + o];
#pragma unroll
        for (int bb = 0; bb < 16; bb++)
            acc[bb] += xs[bb * 2 + bh][c] * wv;
    }
#pragma unroll
    for (int bb = 0; bb < 16; bb++)
        g_outspec[((size_t)(bb * 2 + bh) * M_ + m) * O_ + o] = acc[bb];
}

// ---------------- HMMA bf16-split GEMM: 256x128 CTA tile --------------------
// 8 warps (4m x 2n), warp tile 64x64. KC=64 (128B rows), 2-stage cp.async.
// A frags double-buffered; B frags single-buffered with scheduled reloads.
#define KC        64
#define A_MATB    32768         // 256 rows x 128 B
#define B_MATB    16384         // 128 rows x 128 B
#define STAGEB    98304         // Ah, Al, Bh, Bl
#define OFF_AL    32768
#define OFF_BH    65536
#define OFF_BL    81920
#define GEMM_SMEM 196608        // 2 stages

__device__ __forceinline__ void ldsm_A(uint32_t (&ah)[4][4], uint32_t (&al)[4][4],
                                       uint32_t sd, int kk, uint32_t offA, uint32_t xorA, int hk) {
    const uint32_t ch = (uint32_t)(((2 * kk + hk) ^ xorA) << 4);
#pragma unroll
    for (int mi = 0; mi < 4; mi++) {
        ldsm4(ah[mi][0], ah[mi][1], ah[mi][2], ah[mi][3], sd + offA + mi * 2048 + ch);
        ldsm4(al[mi][0], al[mi][1], al[mi][2], al[mi][3], sd + OFF_AL + offA + mi * 2048 + ch);
    }
}
__device__ __forceinline__ void ldsm_B(uint32_t (&bf)[8][2], uint32_t sm, int kk,
                                       uint32_t offB, uint32_t xorB, int hk) {
    const uint32_t ch = (uint32_t)(((2 * kk + hk) ^ xorB) << 4);
#pragma unroll
    for (int nb = 0; nb < 4; nb++) {
        uint32_t r0, r1, r2, r3;
        ldsm4(r0, r1, r2, r3, sm + offB + nb * 2048 + ch);
        bf[nb * 2 + 0][0] = r0; bf[nb * 2 + 0][1] = r2;
        bf[nb * 2 + 1][0] = r1; bf[nb * 2 + 1][1] = r3;
    }
}

template <int MODE>   // 0: K1 (split-K=SPLITK, grid.x=1), 1: K3
__global__ __launch_bounds__(256, 1) void gemm_hmma(float* __restrict__ outp) {
    extern __shared__ char smem[];
    const uint32_t sb = smem_u32(smem);
    const int tid = threadIdx.x, wid = tid >> 5, lane = tid & 31;
    const int rt = blockIdx.x, ks = blockIdx.y, b = blockIdx.z;

    constexpr int LD   = (MODE == 0) ? N_ : M_;
    constexpr int KLEN = (MODE == 0) ? (N_ / SPLITK) : M_;
    constexpr int NS   = KLEN / KC;

    const __nv_bfloat16 *pAh, *pAl, *pBh, *pBl;
    float* po;
    if (MODE == 0) {
        const size_t aoff = (size_t)ks * KLEN;                 // A = full 256 rows of Ut
        const size_t boff = (size_t)b * 128 * N_ + (size_t)ks * KLEN;
        pAh = g_Uthi + aoff; pAl = g_Utlo + aoff;
        pBh = g_xthi + boff; pBl = g_xtlo + boff;
        po = g_part + (size_t)ks * (B_ * M_ * C_) + (size_t)b * (M_ * C_);
    } else {
        const size_t aoff = (size_t)rt * 256 * M_;
        const size_t boff = (size_t)b * 128 * M_;
        pAh = g_Uhi + aoff; pAl = g_Ulo + aoff;
        pBh = g_sthi + boff; pBl = g_stlo + boff;
        po = outp + ((size_t)b * N_ + (size_t)rt * 256) * O_;
    }

    // stage loader: A mats 256x8 chunks (8 iters), B mats 128x8 (4 iters)
    auto load_stage = [&](int s, int kbase) {
        const uint32_t sd = sb + (uint32_t)(s & 1) * STAGEB;
#pragma unroll
        for (int j = 0; j < 8; j++) {
            const int rem = j * 256 + tid;            // 0..2047
            const int row = rem >> 3, ch = rem & 7;
            const uint32_t so = row * 128 + ((ch ^ (row & 7)) << 4);
            const size_t  go = (size_t)row * LD + kbase + ch * 8;
            cp16(sd + so, pAh + go);
            cp16(sd + OFF_AL + so, pAl + go);
        }
#pragma unroll
        for (int j = 0; j < 4; j++) {
            const int rem = j * 256 + tid;            // 0..1023
            const int row = rem >> 3, ch = rem & 7;
            const uint32_t so = row * 128 + ((ch ^ (row & 7)) << 4);
            const size_t  go = (size_t)row * LD + kbase + ch * 8;
            cp16(sd + OFF_BH + so, pBh + go);
            cp16(sd + OFF_BL + so, pBl + go);
        }
        cp_commit();
    };

    // warp grid 4(m) x 2(n); warp tile 64 x 64
    const int wm = wid >> 1, wn = wid & 1;
    const int lane15 = lane & 15, hk = lane >> 4;
    const uint32_t rowA = wm * 64 + lane15;
    const uint32_t rowB = wn * 64 + lane15;
    const uint32_t offA = rowA * 128, xorA = rowA & 7;
    const uint32_t offB = rowB * 128, xorB = rowB & 7;

    float acc[4][8][4];
#pragma unroll
    for (int i = 0; i < 4; i++)
#pragma unroll
        for (int j = 0; j < 8; j++)
#pragma unroll
            for (int r = 0; r < 4; r++) acc[i][j][r] = 0.f;

    uint32_t ahf[2][4][4], alf[2][4][4];   // A double-buffered
    uint32_t bhf[8][2], blf[8][2];         // B single-buffered

    load_stage(0, 0);
    if (NS > 1) load_stage(1, KC);
    if (NS > 1) asm volatile("cp.async.wait_group 1;" ::: "memory");
    else        asm volatile("cp.async.wait_group 0;" ::: "memory");
    __syncthreads();

    ldsm_A(ahf[0], alf[0], sb, 0, offA, xorA, hk);
    ldsm_B(bhf, sb + OFF_BH, 0, offB, xorB, hk);

    for (int s = 0; s < NS; s++) {
        const uint32_t sd  = sb + (uint32_t)(s & 1) * STAGEB;
        const uint32_t sdn = sb + (uint32_t)((s + 1) & 1) * STAGEB;
#pragma unroll
        for (int kk = 0; kk < 4; kk++) {
            const int p = kk & 1;
            // ---- hh block: prefetch bl[kk], then 32 mmas (ah, bh)
            ldsm_B(blf, sd + OFF_BL, kk, offB, xorB, hk);
#pragma unroll
            for (int mi = 0; mi < 4; mi++)
#pragma unroll
                for (int ni = 0; ni < 8; ni++)
                    mma_bf16(acc[mi][ni], ahf[p][mi], bhf[ni]);
            // ---- stage boundary: old stage smem fully consumed after hh(3)
            if (kk == 3 && s + 1 < NS) {
                asm volatile("cp.async.wait_group 0;" ::: "memory");
                __syncthreads();
                if (s + 2 < NS) load_stage(s + 2, (s + 2) * KC);
            }
            // ---- lh block: prefetch A[kk+1], then 32 mmas (al, bh)
            if (kk < 3)           ldsm_A(ahf[p ^ 1], alf[p ^ 1], sd, kk + 1, offA, xorA, hk);
            else if (s + 1 < NS)  ldsm_A(ahf[p ^ 1], alf[p ^ 1], sdn, 0, offA, xorA, hk);
#pragma unroll
            for (int mi = 0; mi < 4; mi++)
#pragma unroll
                for (int ni = 0; ni < 8; ni++)
                    mma_bf16(acc[mi][ni], alf[p][mi], bhf[ni]);
            // ---- hl block: prefetch bh[kk+1], then 32 mmas (ah, bl)
            if (kk < 3)           ldsm_B(bhf, sd + OFF_BH, kk + 1, offB, xorB, hk);
            else if (s + 1 < NS)  ldsm_B(bhf, sdn + OFF_BH, 0, offB, xorB, hk);
#pragma unroll
            for (int mi = 0; mi < 4; mi++)
#pragma unroll
                for (int ni = 0; ni < 8; ni++)
                    mma_bf16(acc[mi][ni], ahf[p][mi], blf[ni]);
        }
    }

    const int er = (lane >> 2), ec = (lane & 3) * 2;
#pragma unroll
    for (int mi = 0; mi < 4; mi++) {
        const int r0 = wm * 64 + mi * 16 + er;
#pragma unroll
        for (int ni = 0; ni < 8; ni++) {
            const int c = wn * 64 + ni * 8 + ec;
            *(float2*)(po + (size_t)r0 * 128 + c)       = make_float2(acc[mi][ni][0], acc[mi][ni][1]);
            *(float2*)(po + (size_t)(r0 + 8) * 128 + c) = make_float2(acc[mi][ni][2], acc[mi][ni][3]);
        }
    }
}

// ---------------- launch ---------------------------------------------------
extern "C" void kernel_launch(void* const* d_in, const int* in_sizes, int n_in,
                              void* d_out, int out_size) {
    const float* x = (const float*)d_in[0];   // [B, N, C]
    const float* U = (const float*)d_in[1];   // [N, M]
    const float* W = (const float*)d_in[2];   // [C, O, M]
    float* out = (float*)d_out;               // [B, N, O]

    cudaFuncSetAttribute(gemm_hmma<0>, cudaFuncAttributeMaxDynamicSharedMemorySize, GEMM_SMEM);
    cudaFuncSetAttribute(gemm_hmma<1>, cudaFuncAttributeMaxDynamicSharedMemorySize, GEMM_SMEM);

    // prep: splits + transposes
    p1_splitU<<<dim3(M_ / 32, N_ / 32), dim3(32, 8)>>>(U);
    p2_splitx<<<dim3(C_ / 32, N_ / 32, B_), dim3(32, 8)>>>(x);
    k2a_transpose<<<dim3(C_ * O_ / 32, M_ / 32), dim3(32, 8)>>>(W);

    // K1: x_spec = U^T x  (HMMA, 256x128 tile, split-K; reduction fused into k2_mix)
    gemm_hmma<0><<<dim3(1, SPLITK, B_), 256, GEMM_SMEM>>>(nullptr);

    // K2: per-mode channel mixing (fp32)
    k2_mix<<<M_, 256>>>();

    // split S for K3
    p3_splitS<<<dim3(O_ / 32, M_ / 32, B_), dim3(32, 8)>>>();

    // K3: out = U S  (HMMA, 256-row tiles)
    gemm_hmma<1><<<dim3(N_ / 256, 1, B_), 256, GEMM_SMEM>>>(out);
}

// round 8
// speedup vs baseline: 1.1206x; 1.0921x over previous
#include <cuda_runtime.h>
#include <cuda_bf16.h>
#include <cstdint>

#define B_   32
#define N_   4096
#define C_   128
#define O_   128
#define M_   256
#define SPLITK 2

// ---------------- scratch (device globals; no allocation allowed) ----------
__device__ __align__(16) float g_wt[M_ * C_ * O_];        // [m][c][o]
__device__ __align__(16) float g_part[SPLITK * B_ * M_ * C_];  // split-K partials

__device__ __align__(128) __nv_bfloat16 g_Uhi[N_ * M_];   // [n][m]  (A for K3)
__device__ __align__(128) __nv_bfloat16 g_Ulo[N_ * M_];
__device__ __align__(128) __nv_bfloat16 g_Uthi[M_ * N_];  // [m][n]  (A for K1)
__device__ __align__(128) __nv_bfloat16 g_Utlo[M_ * N_];
__device__ __align__(128) __nv_bfloat16 g_xthi[(size_t)B_ * C_ * N_]; // [b][c][n] (B for K1)
__device__ __align__(128) __nv_bfloat16 g_xtlo[(size_t)B_ * C_ * N_];
__device__ __align__(128) __nv_bfloat16 g_shi[B_ * M_ * O_];  // [b][m][o] (B for K3, trans-ldsm)
__device__ __align__(128) __nv_bfloat16 g_slo[B_ * M_ * O_];

// ---------------- helpers ---------------------------------------------------
__device__ __forceinline__ uint32_t smem_u32(const void* p) {
    uint32_t a;
    asm("{ .reg .u64 t; cvta.to.shared.u64 t, %1; cvt.u32.u64 %0, t; }" : "=r"(a) : "l"(p));
    return a;
}
__device__ __forceinline__ void cp16(uint32_t dst, const void* src) {
    asm volatile("cp.async.cg.shared.global [%0], [%1], 16;" :: "r"(dst), "l"(src));
}
__device__ __forceinline__ void cp_commit() {
    asm volatile("cp.async.commit_group;" ::: "memory");
}
__device__ __forceinline__ void ldsm4(uint32_t& r0, uint32_t& r1, uint32_t& r2, uint32_t& r3,
                                      uint32_t addr) {
    asm volatile("ldmatrix.sync.aligned.m8n8.x4.shared.b16 {%0,%1,%2,%3}, [%4];"
                 : "=r"(r0), "=r"(r1), "=r"(r2), "=r"(r3) : "r"(addr));
}
__device__ __forceinline__ void ldsm4t(uint32_t& r0, uint32_t& r1, uint32_t& r2, uint32_t& r3,
                                       uint32_t addr) {
    asm volatile("ldmatrix.sync.aligned.m8n8.x4.trans.shared.b16 {%0,%1,%2,%3}, [%4];"
                 : "=r"(r0), "=r"(r1), "=r"(r2), "=r"(r3) : "r"(addr));
}
__device__ __forceinline__ void mma_bf16(float* d, const uint32_t* a, const uint32_t* b) {
    asm volatile("mma.sync.aligned.m16n8k16.row.col.f32.bf16.bf16.f32 "
                 "{%0,%1,%2,%3}, {%4,%5,%6,%7}, {%8,%9}, {%0,%1,%2,%3};"
                 : "+f"(d[0]), "+f"(d[1]), "+f"(d[2]), "+f"(d[3])
                 : "r"(a[0]), "r"(a[1]), "r"(a[2]), "r"(a[3]), "r"(b[0]), "r"(b[1]));
}
__device__ __forceinline__ void split2(float v, __nv_bfloat16& h, __nv_bfloat16& l) {
    h = __float2bfloat16_rn(v);
    l = __float2bfloat16_rn(v - __bfloat162float(h));
}

// ---------------- prep kernels ---------------------------------------------
__global__ __launch_bounds__(256) void p1_splitU(const float* __restrict__ U) {
    __shared__ float t[32][33];
    const int m0 = blockIdx.x * 32, n0 = blockIdx.y * 32;
    const int tx = threadIdx.x, ty = threadIdx.y;
#pragma unroll
    for (int i = 0; i < 32; i += 8) {
        float v = U[(size_t)(n0 + ty + i) * M_ + m0 + tx];
        t[ty + i][tx] = v;
        __nv_bfloat16 h, l; split2(v, h, l);
        g_Uhi[(size_t)(n0 + ty + i) * M_ + m0 + tx] = h;
        g_Ulo[(size_t)(n0 + ty + i) * M_ + m0 + tx] = l;
    }
    __syncthreads();
#pragma unroll
    for (int i = 0; i < 32; i += 8) {
        float v = t[tx][ty + i];
        __nv_bfloat16 h, l; split2(v, h, l);
        g_Uthi[(size_t)(m0 + ty + i) * N_ + n0 + tx] = h;
        g_Utlo[(size_t)(m0 + ty + i) * N_ + n0 + tx] = l;
    }
}

__global__ __launch_bounds__(256) void p2_splitx(const float* __restrict__ x) {
    __shared__ float t[32][33];
    const int c0 = blockIdx.x * 32, n0 = blockIdx.y * 32, b = blockIdx.z;
    const int tx = threadIdx.x, ty = threadIdx.y;
#pragma unroll
    for (int i = 0; i < 32; i += 8)
        t[ty + i][tx] = x[((size_t)b * N_ + n0 + ty + i) * C_ + c0 + tx];
    __syncthreads();
#pragma unroll
    for (int i = 0; i < 32; i += 8) {
        float v = t[tx][ty + i];
        __nv_bfloat16 h, l; split2(v, h, l);
        g_xthi[((size_t)b * C_ + c0 + ty + i) * N_ + n0 + tx] = h;
        g_xtlo[((size_t)b * C_ + c0 + ty + i) * N_ + n0 + tx] = l;
    }
}

__global__ __launch_bounds__(256) void k2a_transpose(const float* __restrict__ W) {
    __shared__ float t[32][33];
    const int co0 = blockIdx.x * 32, m0 = blockIdx.y * 32;
    const int tx = threadIdx.x, ty = threadIdx.y;
#pragma unroll
    for (int i = 0; i < 32; i += 8)
        t[ty + i][tx] = W[(size_t)(co0 + ty + i) * M_ + m0 + tx];
    __syncthreads();
#pragma unroll
    for (int i = 0; i < 32; i += 8)
        g_wt[(size_t)(m0 + ty + i) * (C_ * O_) + co0 + tx] = t[tx][ty + i];
}

// K2: S[b,m,o] = sum_c xspec[b,m,c] * Wt[m][c][o]; xspec = sum of split-K partials.
// Writes S directly as bf16 hi/lo in [b][m][o] (K3 consumes via trans-ldmatrix).
__global__ __launch_bounds__(256) void k2_mix() {
    __shared__ float xs[B_][C_];
    const int m = blockIdx.x;
    const int tid = threadIdx.x;
    for (int i = tid; i < B_ * C_; i += 256) {
        int b = i >> 7, c = i & 127;
        const size_t idx = ((size_t)b * M_ + m) * C_ + c;
        float v = 0.f;
#pragma unroll
        for (int ks = 0; ks < SPLITK; ks++)
            v += g_part[(size_t)ks * (B_ * M_ * C_) + idx];
        xs[b][c] = v;
    }
    __syncthreads();
    const int o = tid & 127;
    const int bh = tid >> 7;
    const float* w = g_wt + (size_t)m * C_ * O_;
    float acc[16];
#pragma unroll
    for (int i = 0; i < 16; i++) acc[i] = 0.f;
#pragma unroll 4
    for (int c = 0; c < C_; c++) {
        float wv = w[c * O_ + o];
#pragma unroll
        for (int bb = 0; bb < 16; bb++)
            acc[bb] += xs[bb * 2 + bh][c] * wv;
    }
#pragma unroll
    for (int bb = 0; bb < 16; bb++) {
        const int b = bb * 2 + bh;
        __nv_bfloat16 h, l; split2(acc[bb], h, l);
        g_shi[((size_t)b * M_ + m) * O_ + o] = h;
        g_slo[((size_t)b * M_ + m) * O_ + o] = l;
    }
}

// ---------------- HMMA bf16-split GEMM (R4 core, 3-stage, trans-B for K3) ---
#define KC        64
#define MATB      16384
#define OFF_AL    16384
#define OFF_BH    32768
#define OFF_BL    49152
#define STAGEB    65536
#define GEMM_SMEM 196608        // 3 stages

__device__ __forceinline__ void ldsm_A(uint32_t (&ah)[4][4], uint32_t (&al)[4][4],
                                       uint32_t sd, int kk, uint32_t offA, uint32_t xorA, int hk) {
    const uint32_t ch = (uint32_t)(((2 * kk + hk) ^ xorA) << 4);
#pragma unroll
    for (int mi = 0; mi < 4; mi++) {
        ldsm4(ah[mi][0], ah[mi][1], ah[mi][2], ah[mi][3], sd + offA + mi * 2048 + ch);
        ldsm4(al[mi][0], al[mi][1], al[mi][2], al[mi][3], sd + OFF_AL + offA + mi * 2048 + ch);
    }
}

// MODE 0: B tile [128 n-rows][64 k] (K-major), non-trans ldmatrix
__device__ __forceinline__ void ldsm_B0(uint32_t (&bf)[4][2], uint32_t sm, int kk,
                                        uint32_t offB, uint32_t xorB, int hk) {
    const uint32_t ch = (uint32_t)(((2 * kk + hk) ^ xorB) << 4);
#pragma unroll
    for (int nb = 0; nb < 2; nb++) {
        uint32_t r0, r1, r2, r3;
        ldsm4(r0, r1, r2, r3, sm + offB + nb * 2048 + ch);
        bf[nb * 2 + 0][0] = r0; bf[nb * 2 + 0][1] = r2;
        bf[nb * 2 + 1][0] = r1; bf[nb * 2 + 1][1] = r3;
    }
}

// MODE 1: B tile [64 k(m)-rows][128 o] (MN-major), trans ldmatrix
__device__ __forceinline__ void ldsm_B1(uint32_t (&bf)[4][2], uint32_t sm, int kk,
                                        int wn, int lane) {
    const int sel = lane >> 3;
    const int rl = (lane & 7) + ((sel & 1) << 3);
#pragma unroll
    for (int og = 0; og < 2; og++) {
        const int row = kk * 16 + rl;
        const int och = wn * 4 + og * 2 + (sel >> 1);
        const uint32_t addr = sm + (uint32_t)row * 256
                            + (uint32_t)((och ^ ((row & 7) << 1)) << 4);
        uint32_t r0, r1, r2, r3;
        ldsm4t(r0, r1, r2, r3, addr);
        bf[og * 2 + 0][0] = r0; bf[og * 2 + 0][1] = r1;
        bf[og * 2 + 1][0] = r2; bf[og * 2 + 1][1] = r3;
    }
}

template <int MODE>   // 0: K1 (split-K=SPLITK), 1: K3
__global__ __launch_bounds__(256, 1) void gemm_hmma(float* __restrict__ outp) {
    extern __shared__ char smem[];
    const uint32_t sb = smem_u32(smem);
    const int tid = threadIdx.x, wid = tid >> 5, lane = tid & 31;
    const int rt = blockIdx.x, ks = blockIdx.y, b = blockIdx.z;

    constexpr int LD_A = (MODE == 0) ? N_ : M_;
    constexpr int KLEN = (MODE == 0) ? (N_ / SPLITK) : M_;
    constexpr int NS   = KLEN / KC;

    const __nv_bfloat16 *pAh, *pAl, *pBh, *pBl;
    float* po;
    if (MODE == 0) {
        const size_t aoff = (size_t)rt * 128 * N_ + (size_t)ks * KLEN;
        const size_t boff = (size_t)b * 128 * N_ + (size_t)ks * KLEN;
        pAh = g_Uthi + aoff; pAl = g_Utlo + aoff;
        pBh = g_xthi + boff; pBl = g_xtlo + boff;
        po = g_part + (size_t)ks * (B_ * M_ * C_) + (size_t)(b * 2 + rt) * (128 * 128);
    } else {
        const size_t aoff = (size_t)rt * 128 * M_;
        const size_t boff = (size_t)b * M_ * O_;
        pAh = g_Uhi + aoff; pAl = g_Ulo + aoff;
        pBh = g_shi + boff; pBl = g_slo + boff;
        po = outp + ((size_t)b * N_ + (size_t)rt * 128) * O_;
    }

    auto load_stage = [&](int s, int kbase) {
        const uint32_t sd = sb + (uint32_t)(s % 3) * STAGEB;
#pragma unroll
        for (int j = 0; j < 4; j++) {               // A hi/lo: 128 rows x 8 chunks
            const int rem = j * 256 + tid;
            const int row = rem >> 3, ch = rem & 7;
            const uint32_t so = row * 128 + ((ch ^ (row & 7)) << 4);
            const size_t  go = (size_t)row * LD_A + kbase + ch * 8;
            cp16(sd + so, pAh + go);
            cp16(sd + OFF_AL + so, pAl + go);
        }
        if (MODE == 0) {
#pragma unroll
            for (int j = 0; j < 4; j++) {           // B: 128 c-rows x 8 chunks (K-major)
                const int rem = j * 256 + tid;
                const int row = rem >> 3, ch = rem & 7;
                const uint32_t so = row * 128 + ((ch ^ (row & 7)) << 4);
                const size_t  go = (size_t)row * N_ + kbase + ch * 8;
                cp16(sd + OFF_BH + so, pBh + go);
                cp16(sd + OFF_BL + so, pBl + go);
            }
        } else {
#pragma unroll
            for (int j = 0; j < 4; j++) {           // B: 64 m-rows x 16 chunks (o contig)
                const int rem = j * 256 + tid;
                const int row = rem >> 4, ch = rem & 15;
                const uint32_t so = (uint32_t)row * 256 + ((ch ^ ((row & 7) << 1)) << 4);
                const size_t  go = (size_t)(kbase + row) * O_ + ch * 8;
                cp16(sd + OFF_BH + so, pBh + go);
                cp16(sd + OFF_BL + so, pBl + go);
            }
        }
        cp_commit();
    };

    // warp grid 2(m) x 4(n); warp tile 64 x 32
    const int wm = wid >> 2, wn = wid & 3;
    const int lane15 = lane & 15, hk = lane >> 4;
    const uint32_t rowA = wm * 64 + lane15;
    const uint32_t offA = rowA * 128, xorA = rowA & 7;
    const uint32_t rowB = wn * 32 + lane15;
    const uint32_t offB = rowB * 128, xorB = rowB & 7;   // MODE 0 only

    float acc[4][4][4];
#pragma unroll
    for (int i = 0; i < 4; i++)
#pragma unroll
        for (int j = 0; j < 4; j++)
#pragma unroll
            for (int r = 0; r < 4; r++) acc[i][j][r] = 0.f;

    uint32_t ahf[2][4][4], alf[2][4][4];
    uint32_t bhf[4][2], blf[4][2];

    auto ldB = [&](uint32_t (&bf)[4][2], uint32_t sd_base, uint32_t mat_off, int kk) {
        if (MODE == 0) ldsm_B0(bf, sd_base + mat_off, kk, offB, xorB, hk);
        else           ldsm_B1(bf, sd_base + mat_off, kk, wn, lane);
    };

    load_stage(0, 0);
    if (NS > 1) load_stage(1, KC);
    if (NS > 1) asm volatile("cp.async.wait_group 1;" ::: "memory");
    else        asm volatile("cp.async.wait_group 0;" ::: "memory");
    __syncthreads();

    ldsm_A(ahf[0], alf[0], sb, 0, offA, xorA, hk);
    ldB(bhf, sb, OFF_BH, 0);

    for (int s = 0; s < NS; s++) {
        const uint32_t sd  = sb + (uint32_t)(s % 3) * STAGEB;
        const uint32_t sdn = sb + (uint32_t)((s + 1) % 3) * STAGEB;
#pragma unroll
        for (int kk = 0; kk < 4; kk++) {
            const int p = kk & 1;
            // hh block: prefetch bl[kk] (last read of stage s at kk==3)
            ldB(blf, sd, OFF_BL, kk);
#pragma unroll
            for (int mi = 0; mi < 4; mi++)
#pragma unroll
                for (int ni = 0; ni < 4; ni++)
                    mma_bf16(acc[mi][ni], ahf[p][mi], bhf[ni]);
            // stage boundary
            if (kk == 3 && s + 1 < NS) {
                if (s + 2 < NS) {
                    load_stage(s + 2, (s + 2) * KC);
                    asm volatile("cp.async.wait_group 1;" ::: "memory");
                } else {
                    asm volatile("cp.async.wait_group 0;" ::: "memory");
                }
                __syncthreads();
            }
            // lh block: prefetch A[kk+1]
            if (kk < 3)           ldsm_A(ahf[p ^ 1], alf[p ^ 1], sd, kk + 1, offA, xorA, hk);
            else if (s + 1 < NS)  ldsm_A(ahf[p ^ 1], alf[p ^ 1], sdn, 0, offA, xorA, hk);
#pragma unroll
            for (int mi = 0; mi < 4; mi++)
#pragma unroll
                for (int ni = 0; ni < 4; ni++)
                    mma_bf16(acc[mi][ni], alf[p][mi], bhf[ni]);
            // hl block: prefetch bh[kk+1]
            if (kk < 3)           ldB(bhf, sd, OFF_BH, kk + 1);
            else if (s + 1 < NS)  ldB(bhf, sdn, OFF_BH, 0);
#pragma unroll
            for (int mi = 0; mi < 4; mi++)
#pragma unroll
                for (int ni = 0; ni < 4; ni++)
                    mma_bf16(acc[mi][ni], ahf[p][mi], blf[ni]);
        }
    }

    const int er = (lane >> 2), ec = (lane & 3) * 2;
#pragma unroll
    for (int mi = 0; mi < 4; mi++) {
        const int r0 = wm * 64 + mi * 16 + er;
#pragma unroll
        for (int ni = 0; ni < 4; ni++) {
            const int c = wn * 32 + ni * 8 + ec;
            *(float2*)(po + (size_t)r0 * 128 + c)       = make_float2(acc[mi][ni][0], acc[mi][ni][1]);
            *(float2*)(po + (size_t)(r0 + 8) * 128 + c) = make_float2(acc[mi][ni][2], acc[mi][ni][3]);
        }
    }
}

// ---------------- launch ---------------------------------------------------
extern "C" void kernel_launch(void* const* d_in, const int* in_sizes, int n_in,
                              void* d_out, int out_size) {
    const float* x = (const float*)d_in[0];   // [B, N, C]
    const float* U = (const float*)d_in[1];   // [N, M]
    const float* W = (const float*)d_in[2];   // [C, O, M]
    float* out = (float*)d_out;               // [B, N, O]

    cudaFuncSetAttribute(gemm_hmma<0>, cudaFuncAttributeMaxDynamicSharedMemorySize, GEMM_SMEM);
    cudaFuncSetAttribute(gemm_hmma<1>, cudaFuncAttributeMaxDynamicSharedMemorySize, GEMM_SMEM);

    // prep: splits + transposes
    p1_splitU<<<dim3(M_ / 32, N_ / 32), dim3(32, 8)>>>(U);
    p2_splitx<<<dim3(C_ / 32, N_ / 32, B_), dim3(32, 8)>>>(x);
    k2a_transpose<<<dim3(C_ * O_ / 32, M_ / 32), dim3(32, 8)>>>(W);

    // K1: x_spec = U^T x  (HMMA, split-K=2; reduction fused into k2_mix)
    gemm_hmma<0><<<dim3(M_ / 128, SPLITK, B_), 256, GEMM_SMEM>>>(nullptr);

    // K2: per-mode channel mixing (fp32) -> writes S as bf16 hi/lo [b][m][o]
    k2_mix<<<M_, 256>>>();

    // K3: out = U S  (HMMA, B via trans-ldmatrix; no p3 needed)
    gemm_hmma<1><<<dim3(N_ / 128, 1, B_), 256, GEMM_SMEM>>>(out);
}

// round 13
// speedup vs baseline: 1.2907x; 1.1518x over previous
#include <cuda_runtime.h>
#include <cuda_bf16.h>
#include <cstdint>

#define B_   32
#define N_   4096
#define C_   128
#define O_   128
#define M_   256
#define SPLITK 2

// ---------------- scratch (device globals; no allocation allowed) ----------
__device__ __align__(16) float g_wt[M_ * C_ * O_];        // [m][c][o]
__device__ __align__(16) float g_part[SPLITK * B_ * M_ * C_];  // split-K partials

__device__ __align__(128) __nv_bfloat16 g_Uhi[N_ * M_];   // [n][m]  (A for K3)
__device__ __align__(128) __nv_bfloat16 g_Ulo[N_ * M_];
__device__ __align__(128) __nv_bfloat16 g_Uthi[M_ * N_];  // [m][n]  (A for K1)
__device__ __align__(128) __nv_bfloat16 g_Utlo[M_ * N_];
__device__ __align__(128) __nv_bfloat16 g_shi[B_ * M_ * O_];  // [b][m][o] (B for K3)
__device__ __align__(128) __nv_bfloat16 g_slo[B_ * M_ * O_];

// ---------------- helpers ---------------------------------------------------
__device__ __forceinline__ uint32_t smem_u32(const void* p) {
    uint32_t a;
    asm("{ .reg .u64 t; cvta.to.shared.u64 t, %1; cvt.u32.u64 %0, t; }" : "=r"(a) : "l"(p));
    return a;
}
__device__ __forceinline__ void cp16(uint32_t dst, const void* src) {
    asm volatile("cp.async.cg.shared.global [%0], [%1], 16;" :: "r"(dst), "l"(src));
}
__device__ __forceinline__ void cp_commit() {
    asm volatile("cp.async.commit_group;" ::: "memory");
}
__device__ __forceinline__ void sts64(uint32_t addr, uint32_t r0, uint32_t r1) {
    asm volatile("st.shared.v2.b32 [%0], {%1, %2};" :: "r"(addr), "r"(r0), "r"(r1) : "memory");
}
__device__ __forceinline__ void ldsm4(uint32_t& r0, uint32_t& r1, uint32_t& r2, uint32_t& r3,
                                      uint32_t addr) {
    asm volatile("ldmatrix.sync.aligned.m8n8.x4.shared.b16 {%0,%1,%2,%3}, [%4];"
                 : "=r"(r0), "=r"(r1), "=r"(r2), "=r"(r3) : "r"(addr));
}
__device__ __forceinline__ void ldsm4t(uint32_t& r0, uint32_t& r1, uint32_t& r2, uint32_t& r3,
                                       uint32_t addr) {
    asm volatile("ldmatrix.sync.aligned.m8n8.x4.trans.shared.b16 {%0,%1,%2,%3}, [%4];"
                 : "=r"(r0), "=r"(r1), "=r"(r2), "=r"(r3) : "r"(addr));
}
__device__ __forceinline__ void mma_bf16(float* d, const uint32_t* a, const uint32_t* b) {
    asm volatile("mma.sync.aligned.m16n8k16.row.col.f32.bf16.bf16.f32 "
                 "{%0,%1,%2,%3}, {%4,%5,%6,%7}, {%8,%9}, {%0,%1,%2,%3};"
                 : "+f"(d[0]), "+f"(d[1]), "+f"(d[2]), "+f"(d[3])
                 : "r"(a[0]), "r"(a[1]), "r"(a[2]), "r"(a[3]), "r"(b[0]), "r"(b[1]));
}
__device__ __forceinline__ void split2(float v, __nv_bfloat16& h, __nv_bfloat16& l) {
    h = __float2bfloat16_rn(v);
    l = __float2bfloat16_rn(v - __bfloat162float(h));
}
__device__ __forceinline__ uint32_t pack_bf16(__nv_bfloat16 a, __nv_bfloat16 b) {
    __nv_bfloat162 t = __halves2bfloat162(a, b);
    return *(uint32_t*)&t;
}

// ---------------- prep kernels ---------------------------------------------
__global__ __launch_bounds__(256) void p1_splitU(const float* __restrict__ U) {
    __shared__ float t[32][33];
    const int m0 = blockIdx.x * 32, n0 = blockIdx.y * 32;
    const int tx = threadIdx.x, ty = threadIdx.y;
#pragma unroll
    for (int i = 0; i < 32; i += 8) {
        float v = U[(size_t)(n0 + ty + i) * M_ + m0 + tx];
        t[ty + i][tx] = v;
        __nv_bfloat16 h, l; split2(v, h, l);
        g_Uhi[(size_t)(n0 + ty + i) * M_ + m0 + tx] = h;
        g_Ulo[(size_t)(n0 + ty + i) * M_ + m0 + tx] = l;
    }
    __syncthreads();
#pragma unroll
    for (int i = 0; i < 32; i += 8) {
        float v = t[tx][ty + i];
        __nv_bfloat16 h, l; split2(v, h, l);
        g_Uthi[(size_t)(m0 + ty + i) * N_ + n0 + tx] = h;
        g_Utlo[(size_t)(m0 + ty + i) * N_ + n0 + tx] = l;
    }
}

__global__ __launch_bounds__(256) void k2a_transpose(const float* __restrict__ W) {
    __shared__ float t[32][33];
    const int co0 = blockIdx.x * 32, m0 = blockIdx.y * 32;
    const int tx = threadIdx.x, ty = threadIdx.y;
#pragma unroll
    for (int i = 0; i < 32; i += 8)
        t[ty + i][tx] = W[(size_t)(co0 + ty + i) * M_ + m0 + tx];
    __syncthreads();
#pragma unroll
    for (int i = 0; i < 32; i += 8)
        g_wt[(size_t)(m0 + ty + i) * (C_ * O_) + co0 + tx] = t[tx][ty + i];
}

// K2: S[b,m,o] = sum_c xspec[b,m,c] * Wt[m][c][o]; xspec = sum of split-K partials.
// Writes S directly as bf16 hi/lo in [b][m][o] (K3 consumes via trans-ldmatrix).
__global__ __launch_bounds__(256) void k2_mix() {
    __shared__ float xs[B_][C_];
    const int m = blockIdx.x;
    const int tid = threadIdx.x;
    for (int i = tid; i < B_ * C_; i += 256) {
        int b = i >> 7, c = i & 127;
        const size_t idx = ((size_t)b * M_ + m) * C_ + c;
        float v = 0.f;
#pragma unroll
        for (int ks = 0; ks < SPLITK; ks++)
            v += g_part[(size_t)ks * (B_ * M_ * C_) + idx];
        xs[b][c] = v;
    }
    __syncthreads();
    const int o = tid & 127;
    const int bh = tid >> 7;
    const float* w = g_wt + (size_t)m * C_ * O_;
    float acc[16];
#pragma unroll
    for (int i = 0; i < 16; i++) acc[i] = 0.f;
#pragma unroll 4
    for (int c = 0; c < C_; c++) {
        float wv = w[c * O_ + o];
#pragma unroll
        for (int bb = 0; bb < 16; bb++)
            acc[bb] += xs[bb * 2 + bh][c] * wv;
    }
#pragma unroll
    for (int bb = 0; bb < 16; bb++) {
        const int b = bb * 2 + bh;
        __nv_bfloat16 h, l; split2(acc[bb], h, l);
        g_shi[((size_t)b * M_ + m) * O_ + o] = h;
        g_slo[((size_t)b * M_ + m) * O_ + o] = l;
    }
}

// ---------------- HMMA bf16-split GEMM -------------------------------------
// A: K-major bf16 hi/lo via cp.async (128 rows x 64 k, XOR-8 swizzle).
// B: MN-major [64 k-rows][128 cols], 256B rows, swizzle ch^((row&7)<<1),
//    consumed via trans-ldmatrix. MODE0 fills B from fp32 x (LDG+cvt+STS);
//    MODE1 fills from bf16 g_shi/g_slo via cp.async.
#define KC        64
#define MATB      16384
#define OFF_AL    16384
#define OFF_BH    32768
#define OFF_BL    49152
#define STAGEB    65536
#define GEMM_SMEM 196608        // 3 stages

__device__ __forceinline__ void ldsm_A(uint32_t (&ah)[4][4], uint32_t (&al)[4][4],
                                       uint32_t sd, int kk, uint32_t offA, uint32_t xorA, int hk) {
    const uint32_t ch = (uint32_t)(((2 * kk + hk) ^ xorA) << 4);
#pragma unroll
    for (int mi = 0; mi < 4; mi++) {
        ldsm4(ah[mi][0], ah[mi][1], ah[mi][2], ah[mi][3], sd + offA + mi * 2048 + ch);
        ldsm4(al[mi][0], al[mi][1], al[mi][2], al[mi][3], sd + OFF_AL + offA + mi * 2048 + ch);
    }
}

// B tile [64 k-rows][128 cols] (MN-major), trans ldmatrix
__device__ __forceinline__ void ldsm_Bt(uint32_t (&bf)[4][2], uint32_t sm, int kk,
                                        int wn, int lane) {
    const int sel = lane >> 3;
    const int rl = (lane & 7) + ((sel & 1) << 3);
#pragma unroll
    for (int og = 0; og < 2; og++) {
        const int row = kk * 16 + rl;
        const int och = wn * 4 + og * 2 + (sel >> 1);
        const uint32_t addr = sm + (uint32_t)row * 256
                            + (uint32_t)((och ^ ((row & 7) << 1)) << 4);
        uint32_t r0, r1, r2, r3;
        ldsm4t(r0, r1, r2, r3, addr);
        bf[og * 2 + 0][0] = r0; bf[og * 2 + 0][1] = r1;
        bf[og * 2 + 1][0] = r2; bf[og * 2 + 1][1] = r3;
    }
}

template <int MODE>   // 0: K1 (split-K=SPLITK, B from fp32 x), 1: K3
__global__ __launch_bounds__(256, 1) void gemm_hmma(const float* __restrict__ xin,
                                                    float* __restrict__ outp) {
    extern __shared__ char smem[];
    const uint32_t sb = smem_u32(smem);
    const int tid = threadIdx.x, wid = tid >> 5, lane = tid & 31;
    const int rt = blockIdx.x, ks = blockIdx.y, b = blockIdx.z;

    constexpr int LD_A = (MODE == 0) ? N_ : M_;
    constexpr int KLEN = (MODE == 0) ? (N_ / SPLITK) : M_;
    constexpr int NS   = KLEN / KC;

    const __nv_bfloat16 *pAh, *pAl, *pBh = nullptr, *pBl = nullptr;
    const float* px = nullptr;
    float* po;
    if (MODE == 0) {
        const size_t aoff = (size_t)rt * 128 * N_ + (size_t)ks * KLEN;
        pAh = g_Uthi + aoff; pAl = g_Utlo + aoff;
        px = xin + ((size_t)b * N_ + (size_t)ks * KLEN) * C_;   // x[b][n][c] fp32
        po = g_part + (size_t)ks * (B_ * M_ * C_) + (size_t)(b * 2 + rt) * (128 * 128);
    } else {
        const size_t aoff = (size_t)rt * 128 * M_;
        const size_t boff = (size_t)b * M_ * O_;
        pAh = g_Uhi + aoff; pAl = g_Ulo + aoff;
        pBh = g_shi + boff; pBl = g_slo + boff;
        po = outp + ((size_t)b * N_ + (size_t)rt * 128) * O_;
    }

    // MODE0: B fp32 staging regs (64 rows x 32 float4 = 2048 f4 / 256 thr = 8)
    float4 xreg[8];
    auto ldg_B = [&](int kbase) {
        if (MODE != 0) return;
#pragma unroll
        for (int j = 0; j < 8; j++) {
            const int rem = j * 256 + tid;
            const int row = rem >> 5, f4 = rem & 31;
            xreg[j] = *(const float4*)(px + (size_t)(kbase + row) * C_ + f4 * 4);
        }
    };
    auto sts_B = [&](int s) {
        if (MODE != 0) return;
        const uint32_t sd = sb + (uint32_t)(s % 3) * STAGEB;
#pragma unroll
        for (int j = 0; j < 8; j++) {
            const int rem = j * 256 + tid;
            const int row = rem >> 5, f4 = rem & 31;
            const int chunk = f4 >> 1, half = f4 & 1;
            const uint32_t so = (uint32_t)row * 256
                              + (uint32_t)((chunk ^ ((row & 7) << 1)) << 4) + half * 8;
            const float4 v = xreg[j];
            __nv_bfloat16 h0, l0, h1, l1, h2, l2, h3, l3;
            split2(v.x, h0, l0); split2(v.y, h1, l1);
            split2(v.z, h2, l2); split2(v.w, h3, l3);
            sts64(sd + OFF_BH + so, pack_bf16(h0, h1), pack_bf16(h2, h3));
            sts64(sd + OFF_BL + so, pack_bf16(l0, l1), pack_bf16(l2, l3));
        }
    };

    auto load_stage = [&](int s, int kbase) {
        const uint32_t sd = sb + (uint32_t)(s % 3) * STAGEB;
#pragma unroll
        for (int j = 0; j < 4; j++) {               // A hi/lo: 128 rows x 8 chunks
            const int rem = j * 256 + tid;
            const int row = rem >> 3, ch = rem & 7;
            const uint32_t so = row * 128 + ((ch ^ (row & 7)) << 4);
            const size_t  go = (size_t)row * LD_A + kbase + ch * 8;
            cp16(sd + so, pAh + go);
            cp16(sd + OFF_AL + so, pAl + go);
        }
        if (MODE == 1) {
#pragma unroll
            for (int j = 0; j < 4; j++) {           // B: 64 m-rows x 16 chunks (o contig)
                const int rem = j * 256 + tid;
                const int row = rem >> 4, ch = rem & 15;
                const uint32_t so = (uint32_t)row * 256 + ((ch ^ ((row & 7) << 1)) << 4);
                const size_t  go = (size_t)(kbase + row) * O_ + ch * 8;
                cp16(sd + OFF_BH + so, pBh + go);
                cp16(sd + OFF_BL + so, pBl + go);
            }
        }
        cp_commit();
    };

    // warp grid 2(m) x 4(n); warp tile 64 x 32
    const int wm = wid >> 2, wn = wid & 3;
    const int lane15 = lane & 15, hk = lane >> 4;
    const uint32_t rowA = wm * 64 + lane15;
    const uint32_t offA = rowA * 128, xorA = rowA & 7;

    float acc[4][4][4];
#pragma unroll
    for (int i = 0; i < 4; i++)
#pragma unroll
        for (int j = 0; j < 4; j++)
#pragma unroll
            for (int r = 0; r < 4; r++) acc[i][j][r] = 0.f;

    uint32_t ahf[2][4][4], alf[2][4][4];
    uint32_t bhf[4][2], blf[4][2];

    // ---- prologue: stages 0,1 ----
    ldg_B(0);
    load_stage(0, 0);
    sts_B(0);
    if (NS > 1) { ldg_B(KC); load_stage(1, KC); sts_B(1); }
    if (NS > 1) asm volatile("cp.async.wait_group 1;" ::: "memory");
    else        asm volatile("cp.async.wait_group 0;" ::: "memory");
    __syncthreads();

    ldsm_A(ahf[0], alf[0], sb, 0, offA, xorA, hk);
    ldsm_Bt(bhf, sb + OFF_BH, 0, wn, lane);

    for (int s = 0; s < NS; s++) {
        const uint32_t sd  = sb + (uint32_t)(s % 3) * STAGEB;
        const uint32_t sdn = sb + (uint32_t)((s + 1) % 3) * STAGEB;
#pragma unroll
        for (int kk = 0; kk < 4; kk++) {
            const int p = kk & 1;
            // hh block: prefetch bl[kk]
            ldsm_Bt(blf, sd + OFF_BL, kk, wn, lane);
#pragma unroll
            for (int mi = 0; mi < 4; mi++)
#pragma unroll
                for (int ni = 0; ni < 4; ni++)
                    mma_bf16(acc[mi][ni], ahf[p][mi], bhf[ni]);
            // issue next-next stage's B LDGs early (latency hides under 1 stage of mma)
            if (kk == 0 && s + 2 < NS) ldg_B((s + 2) * KC);
            // stage boundary
            if (kk == 3 && s + 1 < NS) {
                if (s + 2 < NS) {
                    sts_B(s + 2);                         // convert + STS into free buffer
                    load_stage(s + 2, (s + 2) * KC);      // A (and MODE1 B) cp.async
                    asm volatile("cp.async.wait_group 1;" ::: "memory");
                } else {
                    asm volatile("cp.async.wait_group 0;" ::: "memory");
                }
                __syncthreads();
            }
            // lh block: prefetch A[kk+1]
            if (kk < 3)           ldsm_A(ahf[p ^ 1], alf[p ^ 1], sd, kk + 1, offA, xorA, hk);
            else if (s + 1 < NS)  ldsm_A(ahf[p ^ 1], alf[p ^ 1], sdn, 0, offA, xorA, hk);
#pragma unroll
            for (int mi = 0; mi < 4; mi++)
#pragma unroll
                for (int ni = 0; ni < 4; ni++)
                    mma_bf16(acc[mi][ni], alf[p][mi], bhf[ni]);
            // hl block: prefetch bh[kk+1]
            if (kk < 3)           ldsm_Bt(bhf, sd + OFF_BH, kk + 1, wn, lane);
            else if (s + 1 < NS)  ldsm_Bt(bhf, sdn + OFF_BH, 0, wn, lane);
#pragma unroll
            for (int mi = 0; mi < 4; mi++)
#pragma unroll
                for (int ni = 0; ni < 4; ni++)
                    mma_bf16(acc[mi][ni], ahf[p][mi], blf[ni]);
        }
    }

    const int er = (lane >> 2), ec = (lane & 3) * 2;
#pragma unroll
    for (int mi = 0; mi < 4; mi++) {
        const int r0 = wm * 64 + mi * 16 + er;
#pragma unroll
        for (int ni = 0; ni < 4; ni++) {
            const int c = wn * 32 + ni * 8 + ec;
            *(float2*)(po + (size_t)r0 * 128 + c)       = make_float2(acc[mi][ni][0], acc[mi][ni][1]);
            *(float2*)(po + (size_t)(r0 + 8) * 128 + c) = make_float2(acc[mi][ni][2], acc[mi][ni][3]);
        }
    }
}

// ---------------- launch ---------------------------------------------------
extern "C" void kernel_launch(void* const* d_in, const int* in_sizes, int n_in,
                              void* d_out, int out_size) {
    const float* x = (const float*)d_in[0];   // [B, N, C]
    const float* U = (const float*)d_in[1];   // [N, M]
    const float* W = (const float*)d_in[2];   // [C, O, M]
    float* out = (float*)d_out;               // [B, N, O]

    cudaFuncSetAttribute(gemm_hmma<0>, cudaFuncAttributeMaxDynamicSharedMemorySize, GEMM_SMEM);
    cudaFuncSetAttribute(gemm_hmma<1>, cudaFuncAttributeMaxDynamicSharedMemorySize, GEMM_SMEM);

    // prep: U split + W transpose (x split is fused into K1)
    p1_splitU<<<dim3(M_ / 32, N_ / 32), dim3(32, 8)>>>(U);
    k2a_transpose<<<dim3(C_ * O_ / 32, M_ / 32), dim3(32, 8)>>>(W);

    // K1: x_spec = U^T x  (HMMA, split-K=2; B split fused; reduction fused into k2_mix)
    gemm_hmma<0><<<dim3(M_ / 128, SPLITK, B_), 256, GEMM_SMEM>>>(x, nullptr);

    // K2: per-mode channel mixing (fp32) -> writes S as bf16 hi/lo [b][m][o]
    k2_mix<<<M_, 256>>>();

    // K3: out = U S  (HMMA, B via trans-ldmatrix)
    gemm_hmma<1><<<dim3(N_ / 128, 1, B_), 256, GEMM_SMEM>>>(nullptr, out);
}

// round 16
// speedup vs baseline: 1.4510x; 1.1242x over previous
#include <cuda_runtime.h>
#include <cuda_bf16.h>
#include <cstdint>

#define B_   32
#define N_   4096
#define C_   128
#define O_   128
#define M_   256
#define SPLITK 2

// ---------------- scratch (device globals; no allocation allowed) ----------
__device__ __align__(16) float g_wt[M_ * C_ * O_];        // [m][c][o]
__device__ __align__(16) float g_part[SPLITK * B_ * M_ * C_];  // split-K partials

__device__ __align__(128) __nv_bfloat16 g_Uhi[N_ * M_];   // [n][m]  (A for K3)
__device__ __align__(128) __nv_bfloat16 g_Ulo[N_ * M_];
__device__ __align__(128) __nv_bfloat16 g_Uthi[M_ * N_];  // [m][n]  (A for K1)
__device__ __align__(128) __nv_bfloat16 g_Utlo[M_ * N_];
__device__ __align__(128) __nv_bfloat16 g_shi[B_ * M_ * O_];  // [b][m][o] (B for K3)
__device__ __align__(128) __nv_bfloat16 g_slo[B_ * M_ * O_];

// ---------------- helpers ---------------------------------------------------
__device__ __forceinline__ uint32_t smem_u32(const void* p) {
    uint32_t a;
    asm("{ .reg .u64 t; cvta.to.shared.u64 t, %1; cvt.u32.u64 %0, t; }" : "=r"(a) : "l"(p));
    return a;
}
__device__ __forceinline__ void cp16(uint32_t dst, const void* src) {
    asm volatile("cp.async.cg.shared.global [%0], [%1], 16;" :: "r"(dst), "l"(src));
}
__device__ __forceinline__ void cp_commit() {
    asm volatile("cp.async.commit_group;" ::: "memory");
}
__device__ __forceinline__ void sts64(uint32_t addr, uint32_t r0, uint32_t r1) {
    asm volatile("st.shared.v2.b32 [%0], {%1, %2};" :: "r"(addr), "r"(r0), "r"(r1) : "memory");
}
__device__ __forceinline__ void ldsm4(uint32_t& r0, uint32_t& r1, uint32_t& r2, uint32_t& r3,
                                      uint32_t addr) {
    asm volatile("ldmatrix.sync.aligned.m8n8.x4.shared.b16 {%0,%1,%2,%3}, [%4];"
                 : "=r"(r0), "=r"(r1), "=r"(r2), "=r"(r3) : "r"(addr));
}
__device__ __forceinline__ void ldsm4t(uint32_t& r0, uint32_t& r1, uint32_t& r2, uint32_t& r3,
                                       uint32_t addr) {
    asm volatile("ldmatrix.sync.aligned.m8n8.x4.trans.shared.b16 {%0,%1,%2,%3}, [%4];"
                 : "=r"(r0), "=r"(r1), "=r"(r2), "=r"(r3) : "r"(addr));
}
__device__ __forceinline__ void mma_bf16(float* d, const uint32_t* a, const uint32_t* b) {
    asm volatile("mma.sync.aligned.m16n8k16.row.col.f32.bf16.bf16.f32 "
                 "{%0,%1,%2,%3}, {%4,%5,%6,%7}, {%8,%9}, {%0,%1,%2,%3};"
                 : "+f"(d[0]), "+f"(d[1]), "+f"(d[2]), "+f"(d[3])
                 : "r"(a[0]), "r"(a[1]), "r"(a[2]), "r"(a[3]), "r"(b[0]), "r"(b[1]));
}
__device__ __forceinline__ void split2(float v, __nv_bfloat16& h, __nv_bfloat16& l) {
    h = __float2bfloat16_rn(v);
    l = __float2bfloat16_rn(v - __bfloat162float(h));
}
__device__ __forceinline__ uint32_t pack_bf16(__nv_bfloat16 a, __nv_bfloat16 b) {
    __nv_bfloat162 t = __halves2bfloat162(a, b);
    return *(uint32_t*)&t;
}

// ---------------- prep kernels ---------------------------------------------
__global__ __launch_bounds__(256) void p1_splitU(const float* __restrict__ U) {
    __shared__ float t[32][33];
    const int m0 = blockIdx.x * 32, n0 = blockIdx.y * 32;
    const int tx = threadIdx.x, ty = threadIdx.y;
#pragma unroll
    for (int i = 0; i < 32; i += 8) {
        float v = U[(size_t)(n0 + ty + i) * M_ + m0 + tx];
        t[ty + i][tx] = v;
        __nv_bfloat16 h, l; split2(v, h, l);
        g_Uhi[(size_t)(n0 + ty + i) * M_ + m0 + tx] = h;
        g_Ulo[(size_t)(n0 + ty + i) * M_ + m0 + tx] = l;
    }
    __syncthreads();
#pragma unroll
    for (int i = 0; i < 32; i += 8) {
        float v = t[tx][ty + i];
        __nv_bfloat16 h, l; split2(v, h, l);
        g_Uthi[(size_t)(m0 + ty + i) * N_ + n0 + tx] = h;
        g_Utlo[(size_t)(m0 + ty + i) * N_ + n0 + tx] = l;
    }
}

__global__ __launch_bounds__(256) void k2a_transpose(const float* __restrict__ W) {
    __shared__ float t[32][33];
    const int co0 = blockIdx.x * 32, m0 = blockIdx.y * 32;
    const int tx = threadIdx.x, ty = threadIdx.y;
#pragma unroll
    for (int i = 0; i < 32; i += 8)
        t[ty + i][tx] = W[(size_t)(co0 + ty + i) * M_ + m0 + tx];
    __syncthreads();
#pragma unroll
    for (int i = 0; i < 32; i += 8)
        g_wt[(size_t)(m0 + ty + i) * (C_ * O_) + co0 + tx] = t[tx][ty + i];
}

// K2: S[b,m,o] = sum_c xspec[b,m,c] * Wt[m][c][o]; xspec = sum of split-K partials.
// grid (m, bhalf): each CTA covers 16 b-rows of one mode. W chunks are
// cp.async double-buffered through smem so the c-loop never touches DRAM latency.
#define K2CH 32     // c-rows per W chunk
__global__ __launch_bounds__(256) void k2_mix() {
    __shared__ float xs[16][C_];                 // 8 KB
    __shared__ float wbuf[2][K2CH * O_];         // 32 KB
    const int m = blockIdx.x;
    const int half = blockIdx.y;                 // 0/1 -> b rows [half*16, half*16+16)
    const int tid = threadIdx.x;
    const float* w = g_wt + (size_t)m * C_ * O_;
    const uint32_t wb = smem_u32(wbuf);

    // prefetch W chunk 0 (1024 float4 / 256 thr = 4 each)
#pragma unroll
    for (int j = 0; j < 4; j++) {
        const int e = j * 256 + tid;             // float4 index in chunk
        cp16(wb + e * 16, w + e * 4);
    }
    cp_commit();

    // xs: 16 rows x 128 c = 2048 elems / 256 thr = 8 each
    for (int i = tid; i < 16 * C_; i += 256) {
        const int br = i >> 7, c = i & 127;
        const int b = half * 16 + br;
        const size_t idx = ((size_t)b * M_ + m) * C_ + c;
        float v = 0.f;
#pragma unroll
        for (int ks = 0; ks < SPLITK; ks++)
            v += g_part[(size_t)ks * (B_ * M_ * C_) + idx];
        xs[br][c] = v;
    }

    const int o = tid & 127;
    const int bh = tid >> 7;                     // 0/1
    float acc[8];
#pragma unroll
    for (int i = 0; i < 8; i++) acc[i] = 0.f;

#pragma unroll
    for (int ch = 0; ch < C_ / K2CH; ch++) {
        // prefetch next chunk into the other buffer
        if (ch + 1 < C_ / K2CH) {
            const uint32_t dst = wb + ((ch + 1) & 1) * (K2CH * O_ * 4);
            const float* src = w + (size_t)(ch + 1) * K2CH * O_;
#pragma unroll
            for (int j = 0; j < 4; j++) {
                const int e = j * 256 + tid;
                cp16(dst + e * 16, src + e * 4);
            }
            cp_commit();
            asm volatile("cp.async.wait_group 1;" ::: "memory");
        } else {
            asm volatile("cp.async.wait_group 0;" ::: "memory");
        }
        __syncthreads();
        const float* wc = wbuf[ch & 1];
#pragma unroll
        for (int cc = 0; cc < K2CH; cc++) {
            const float wv = wc[cc * O_ + o];
            const int c = ch * K2CH + cc;
#pragma unroll
            for (int bb = 0; bb < 8; bb++)
                acc[bb] += xs[bb * 2 + bh][c] * wv;
        }
        __syncthreads();
    }

#pragma unroll
    for (int bb = 0; bb < 8; bb++) {
        const int b = half * 16 + bb * 2 + bh;
        __nv_bfloat16 h, l; split2(acc[bb], h, l);
        g_shi[((size_t)b * M_ + m) * O_ + o] = h;
        g_slo[((size_t)b * M_ + m) * O_ + o] = l;
    }
}

// ---------------- HMMA bf16-split GEMM -------------------------------------
// A: K-major bf16 hi/lo via cp.async (128 rows x 64 k, XOR-8 swizzle).
// B: MN-major [64 k-rows][128 cols], 256B rows, swizzle ch^((row&7)<<1),
//    consumed via trans-ldmatrix. MODE0 fills B from fp32 x (LDG+cvt+STS);
//    MODE1 fills from bf16 g_shi/g_slo via cp.async.
#define KC        64
#define MATB      16384
#define OFF_AL    16384
#define OFF_BH    32768
#define OFF_BL    49152
#define STAGEB    65536
#define GEMM_SMEM 196608        // 3 stages

__device__ __forceinline__ void ldsm_A(uint32_t (&ah)[4][4], uint32_t (&al)[4][4],
                                       uint32_t sd, int kk, uint32_t offA, uint32_t xorA, int hk) {
    const uint32_t ch = (uint32_t)(((2 * kk + hk) ^ xorA) << 4);
#pragma unroll
    for (int mi = 0; mi < 4; mi++) {
        ldsm4(ah[mi][0], ah[mi][1], ah[mi][2], ah[mi][3], sd + offA + mi * 2048 + ch);
        ldsm4(al[mi][0], al[mi][1], al[mi][2], al[mi][3], sd + OFF_AL + offA + mi * 2048 + ch);
    }
}

// B tile [64 k-rows][128 cols] (MN-major), trans ldmatrix
__device__ __forceinline__ void ldsm_Bt(uint32_t (&bf)[4][2], uint32_t sm, int kk,
                                        int wn, int lane) {
    const int sel = lane >> 3;
    const int rl = (lane & 7) + ((sel & 1) << 3);
#pragma unroll
    for (int og = 0; og < 2; og++) {
        const int row = kk * 16 + rl;
        const int och = wn * 4 + og * 2 + (sel >> 1);
        const uint32_t addr = sm + (uint32_t)row * 256
                            + (uint32_t)((och ^ ((row & 7) << 1)) << 4);
        uint32_t r0, r1, r2, r3;
        ldsm4t(r0, r1, r2, r3, addr);
        bf[og * 2 + 0][0] = r0; bf[og * 2 + 0][1] = r1;
        bf[og * 2 + 1][0] = r2; bf[og * 2 + 1][1] = r3;
    }
}

template <int MODE>   // 0: K1 (split-K=SPLITK, B from fp32 x), 1: K3
__global__ __launch_bounds__(256, 1) void gemm_hmma(const float* __restrict__ xin,
                                                    float* __restrict__ outp) {
    extern __shared__ char smem[];
    const uint32_t sb = smem_u32(smem);
    const int tid = threadIdx.x, wid = tid >> 5, lane = tid & 31;
    const int rt = blockIdx.x, ks = blockIdx.y, b = blockIdx.z;

    constexpr int LD_A = (MODE == 0) ? N_ : M_;
    constexpr int KLEN = (MODE == 0) ? (N_ / SPLITK) : M_;
    constexpr int NS   = KLEN / KC;

    const __nv_bfloat16 *pAh, *pAl, *pBh = nullptr, *pBl = nullptr;
    const float* px = nullptr;
    float* po;
    if (MODE == 0) {
        const size_t aoff = (size_t)rt * 128 * N_ + (size_t)ks * KLEN;
        pAh = g_Uthi + aoff; pAl = g_Utlo + aoff;
        px = xin + ((size_t)b * N_ + (size_t)ks * KLEN) * C_;   // x[b][n][c] fp32
        po = g_part + (size_t)ks * (B_ * M_ * C_) + (size_t)(b * 2 + rt) * (128 * 128);
    } else {
        const size_t aoff = (size_t)rt * 128 * M_;
        const size_t boff = (size_t)b * M_ * O_;
        pAh = g_Uhi + aoff; pAl = g_Ulo + aoff;
        pBh = g_shi + boff; pBl = g_slo + boff;
        po = outp + ((size_t)b * N_ + (size_t)rt * 128) * O_;
    }

    // MODE0: B fp32 staging regs (64 rows x 32 float4 = 2048 f4 / 256 thr = 8)
    float4 xreg[8];
    auto ldg_B = [&](int kbase) {
        if (MODE != 0) return;
#pragma unroll
        for (int j = 0; j < 8; j++) {
            const int rem = j * 256 + tid;
            const int row = rem >> 5, f4 = rem & 31;
            xreg[j] = *(const float4*)(px + (size_t)(kbase + row) * C_ + f4 * 4);
        }
    };
    auto sts_B = [&](int s) {
        if (MODE != 0) return;
        const uint32_t sd = sb + (uint32_t)(s % 3) * STAGEB;
#pragma unroll
        for (int j = 0; j < 8; j++) {
            const int rem = j * 256 + tid;
            const int row = rem >> 5, f4 = rem & 31;
            const int chunk = f4 >> 1, half = f4 & 1;
            const uint32_t so = (uint32_t)row * 256
                              + (uint32_t)((chunk ^ ((row & 7) << 1)) << 4) + half * 8;
            const float4 v = xreg[j];
            __nv_bfloat16 h0, l0, h1, l1, h2, l2, h3, l3;
            split2(v.x, h0, l0); split2(v.y, h1, l1);
            split2(v.z, h2, l2); split2(v.w, h3, l3);
            sts64(sd + OFF_BH + so, pack_bf16(h0, h1), pack_bf16(h2, h3));
            sts64(sd + OFF_BL + so, pack_bf16(l0, l1), pack_bf16(l2, l3));
        }
    };

    auto load_stage = [&](int s, int kbase) {
        const uint32_t sd = sb + (uint32_t)(s % 3) * STAGEB;
#pragma unroll
        for (int j = 0; j < 4; j++) {               // A hi/lo: 128 rows x 8 chunks
            const int rem = j * 256 + tid;
            const int row = rem >> 3, ch = rem & 7;
            const uint32_t so = row * 128 + ((ch ^ (row & 7)) << 4);
            const size_t  go = (size_t)row * LD_A + kbase + ch * 8;
            cp16(sd + so, pAh + go);
            cp16(sd + OFF_AL + so, pAl + go);
        }
        if (MODE == 1) {
#pragma unroll
            for (int j = 0; j < 4; j++) {           // B: 64 m-rows x 16 chunks (o contig)
                const int rem = j * 256 + tid;
                const int row = rem >> 4, ch = rem & 15;
                const uint32_t so = (uint32_t)row * 256 + ((ch ^ ((row & 7) << 1)) << 4);
                const size_t  go = (size_t)(kbase + row) * O_ + ch * 8;
                cp16(sd + OFF_BH + so, pBh + go);
                cp16(sd + OFF_BL + so, pBl + go);
            }
        }
        cp_commit();
    };

    // warp grid 2(m) x 4(n); warp tile 64 x 32
    const int wm = wid >> 2, wn = wid & 3;
    const int lane15 = lane & 15, hk = lane >> 4;
    const uint32_t rowA = wm * 64 + lane15;
    const uint32_t offA = rowA * 128, xorA = rowA & 7;

    float acc[4][4][4];
#pragma unroll
    for (int i = 0; i < 4; i++)
#pragma unroll
        for (int j = 0; j < 4; j++)
#pragma unroll
            for (int r = 0; r < 4; r++) acc[i][j][r] = 0.f;

    uint32_t ahf[2][4][4], alf[2][4][4];
    uint32_t bhf[4][2], blf[4][2];

    // ---- prologue: stages 0,1 ----
    ldg_B(0);
    load_stage(0, 0);
    sts_B(0);
    if (NS > 1) { ldg_B(KC); load_stage(1, KC); sts_B(1); }
    if (NS > 1) asm volatile("cp.async.wait_group 1;" ::: "memory");
    else        asm volatile("cp.async.wait_group 0;" ::: "memory");
    __syncthreads();

    ldsm_A(ahf[0], alf[0], sb, 0, offA, xorA, hk);
    ldsm_Bt(bhf, sb + OFF_BH, 0, wn, lane);

    for (int s = 0; s < NS; s++) {
        const uint32_t sd  = sb + (uint32_t)(s % 3) * STAGEB;
        const uint32_t sdn = sb + (uint32_t)((s + 1) % 3) * STAGEB;
#pragma unroll
        for (int kk = 0; kk < 4; kk++) {
            const int p = kk & 1;
            // hh block: prefetch bl[kk]
            ldsm_Bt(blf, sd + OFF_BL, kk, wn, lane);
#pragma unroll
            for (int mi = 0; mi < 4; mi++)
#pragma unroll
                for (int ni = 0; ni < 4; ni++)
                    mma_bf16(acc[mi][ni], ahf[p][mi], bhf[ni]);
            // issue next-next stage's B LDGs early (latency hides under 1 stage of mma)
            if (kk == 0 && s + 2 < NS) ldg_B((s + 2) * KC);
            // stage boundary
            if (kk == 3 && s + 1 < NS) {
                if (s + 2 < NS) {
                    sts_B(s + 2);                         // convert + STS into free buffer
                    load_stage(s + 2, (s + 2) * KC);      // A (and MODE1 B) cp.async
                    asm volatile("cp.async.wait_group 1;" ::: "memory");
                } else {
                    asm volatile("cp.async.wait_group 0;" ::: "memory");
                }
                __syncthreads();
            }
            // lh block: prefetch A[kk+1]
            if (kk < 3)           ldsm_A(ahf[p ^ 1], alf[p ^ 1], sd, kk + 1, offA, xorA, hk);
            else if (s + 1 < NS)  ldsm_A(ahf[p ^ 1], alf[p ^ 1], sdn, 0, offA, xorA, hk);
#pragma unroll
            for (int mi = 0; mi < 4; mi++)
#pragma unroll
                for (int ni = 0; ni < 4; ni++)
                    mma_bf16(acc[mi][ni], alf[p][mi], bhf[ni]);
            // hl block: prefetch bh[kk+1]
            if (kk < 3)           ldsm_Bt(bhf, sd + OFF_BH, kk + 1, wn, lane);
            else if (s + 1 < NS)  ldsm_Bt(bhf, sdn + OFF_BH, 0, wn, lane);
#pragma unroll
            for (int mi = 0; mi < 4; mi++)
#pragma unroll
                for (int ni = 0; ni < 4; ni++)
                    mma_bf16(acc[mi][ni], ahf[p][mi], blf[ni]);
        }
    }

    const int er = (lane >> 2), ec = (lane & 3) * 2;
#pragma unroll
    for (int mi = 0; mi < 4; mi++) {
        const int r0 = wm * 64 + mi * 16 + er;
#pragma unroll
        for (int ni = 0; ni < 4; ni++) {
            const int c = wn * 32 + ni * 8 + ec;
            *(float2*)(po + (size_t)r0 * 128 + c)       = make_float2(acc[mi][ni][0], acc[mi][ni][1]);
            *(float2*)(po + (size_t)(r0 + 8) * 128 + c) = make_float2(acc[mi][ni][2], acc[mi][ni][3]);
        }
    }
}

// ---------------- launch ---------------------------------------------------
extern "C" void kernel_launch(void* const* d_in, const int* in_sizes, int n_in,
                              void* d_out, int out_size) {
    const float* x = (const float*)d_in[0];   // [B, N, C]
    const float* U = (const float*)d_in[1];   // [N, M]
    const float* W = (const float*)d_in[2];   // [C, O, M]
    float* out = (float*)d_out;               // [B, N, O]

    cudaFuncSetAttribute(gemm_hmma<0>, cudaFuncAttributeMaxDynamicSharedMemorySize, GEMM_SMEM);
    cudaFuncSetAttribute(gemm_hmma<1>, cudaFuncAttributeMaxDynamicSharedMemorySize, GEMM_SMEM);

    // prep: U split + W transpose (x split is fused into K1)
    p1_splitU<<<dim3(M_ / 32, N_ / 32), dim3(32, 8)>>>(U);
    k2a_transpose<<<dim3(C_ * O_ / 32, M_ / 32), dim3(32, 8)>>>(W);

    // K1: x_spec = U^T x  (HMMA, split-K=2; B split fused; reduction fused into k2_mix)
    gemm_hmma<0><<<dim3(M_ / 128, SPLITK, B_), 256, GEMM_SMEM>>>(x, nullptr);

    // K2: per-mode channel mixing (fp32, W pipelined through smem)
    k2_mix<<<dim3(M_, 2), 256>>>();

    // K3: out = U S  (HMMA, B via trans-ldmatrix)
    gemm_hmma<1><<<dim3(N_ / 128, 1, B_), 256, GEMM_SMEM>>>(nullptr, out);
}